// round 1
// baseline (speedup 1.0000x reference)
#include <cuda_runtime.h>
#include <math.h>

#define T 2048
#define H 1024
#define E 8
#define NI 512          // I
#define SIH 2048        // SI
#define NPAIR (2*T)

// ---- scratch (static device globals; allocation-free) ----
__device__ float g_S1[(size_t)T*SIH];        // shared-expert SwiGLU intermediate  [T,SI]
__device__ float g_shared2[(size_t)T*H];     // shared-expert output               [T,H]
__device__ float g_act[(size_t)NPAIR*NI];    // per-pair SwiGLU (weight-scaled)    [2T,I]
__device__ float g_pairout[(size_t)NPAIR*H]; // per-pair down-proj output          [2T,H]
__device__ int   g_top_e[T*2];
__device__ float g_top_w[T*2];
__device__ float g_gl[T];                    // shared-expert-gate logit
__device__ int   g_count[E];
__device__ int   g_offset[E];
__device__ int   g_fill[E];
__device__ int   g_pair_token[NPAIR];
__device__ float g_pair_w[NPAIR];
__device__ int   g_pos[T*2];                 // token,k -> pair index

// ---- 0: reset counters ----
__global__ void reset_kernel() {
    if (threadIdx.x < E) g_count[threadIdx.x] = 0;
}

// ---- 1: router (one warp per token) ----
__global__ void router_kernel(const float* __restrict__ x,
                              const float* __restrict__ rw,
                              const float* __restrict__ seg) {
    int warp = (blockIdx.x * blockDim.x + threadIdx.x) >> 5;
    int lane = threadIdx.x & 31;
    if (warp >= T) return;
    const float* xr = x + (size_t)warp * H;
    float acc[E];
    #pragma unroll
    for (int e = 0; e < E; e++) acc[e] = 0.f;
    float accg = 0.f;
    for (int k = lane; k < H; k += 32) {
        float xv = xr[k];
        #pragma unroll
        for (int e = 0; e < E; e++) acc[e] += xv * rw[e*H + k];
        accg += xv * seg[k];
    }
    #pragma unroll
    for (int o = 16; o > 0; o >>= 1) {
        #pragma unroll
        for (int e = 0; e < E; e++) acc[e] += __shfl_xor_sync(0xffffffffu, acc[e], o);
        accg += __shfl_xor_sync(0xffffffffu, accg, o);
    }
    if (lane == 0) {
        int be = 0; float bv = acc[0];
        #pragma unroll
        for (int e = 1; e < E; e++) if (acc[e] > bv) { bv = acc[e]; be = e; }
        int se = -1; float sv = -1e30f;
        #pragma unroll
        for (int e = 0; e < E; e++) if (e != be && acc[e] > sv) { sv = acc[e]; se = e; }
        // renormalized top-2 softmax weights: w0 = e^l0/(e^l0+e^l1)
        float w0 = 1.f / (1.f + expf(sv - bv));
        float w1 = 1.f - w0;
        g_top_e[warp*2+0] = be; g_top_e[warp*2+1] = se;
        g_top_w[warp*2+0] = w0; g_top_w[warp*2+1] = w1;
        g_gl[warp] = accg;
        atomicAdd(&g_count[be], 1);
        atomicAdd(&g_count[se], 1);
    }
}

// ---- 2: exclusive scan over E=8 counts ----
__global__ void scan_kernel() {
    if (threadIdx.x == 0) {
        int off = 0;
        for (int e = 0; e < E; e++) {
            g_offset[e] = off;
            g_fill[e] = off;
            off += g_count[e];
        }
    }
}

// ---- 3: scatter tokens into compact per-expert segments ----
__global__ void scatter_kernel() {
    int t = blockIdx.x * blockDim.x + threadIdx.x;
    if (t >= T) return;
    #pragma unroll
    for (int k = 0; k < 2; k++) {
        int e = g_top_e[t*2+k];
        int slot = atomicAdd(&g_fill[e], 1);
        g_pair_token[slot] = t;
        g_pair_w[slot] = g_top_w[t*2+k];
        g_pos[t*2+k] = slot;
    }
}

__device__ __forceinline__ float siluf(float g) {
    return g * (1.f / (1.f + expf(-g)));
}

// ---- 4: shared expert GEMM1 (dual: gate+up, fused SwiGLU) ----
// S1[t,n] = silu(x[t,:]·Wg[n,:]) * (x[t,:]·Wu[n,:]),  M=T, N=SI, K=H
__global__ __launch_bounds__(256) void shared1_kernel(const float* __restrict__ x,
                                                      const float* __restrict__ Wg,
                                                      const float* __restrict__ Wu) {
    __shared__ float As[16][68], Bg[16][68], Bu[16][68];
    int tid = threadIdx.x;
    int tx = tid & 15, ty = tid >> 4;
    int m0 = blockIdx.y * 64, n0 = blockIdx.x * 64;
    int lr = tid >> 2;          // 0..63
    int lc = (tid & 3) * 4;     // 0,4,8,12
    float ag[4][4] = {}, au[4][4] = {};
    for (int k0 = 0; k0 < H; k0 += 16) {
        float4 a  = *(const float4*)&x [(size_t)(m0+lr)*H + k0 + lc];
        float4 bg = *(const float4*)&Wg[(size_t)(n0+lr)*H + k0 + lc];
        float4 bu = *(const float4*)&Wu[(size_t)(n0+lr)*H + k0 + lc];
        As[lc+0][lr]=a.x;  As[lc+1][lr]=a.y;  As[lc+2][lr]=a.z;  As[lc+3][lr]=a.w;
        Bg[lc+0][lr]=bg.x; Bg[lc+1][lr]=bg.y; Bg[lc+2][lr]=bg.z; Bg[lc+3][lr]=bg.w;
        Bu[lc+0][lr]=bu.x; Bu[lc+1][lr]=bu.y; Bu[lc+2][lr]=bu.z; Bu[lc+3][lr]=bu.w;
        __syncthreads();
        #pragma unroll
        for (int kk = 0; kk < 16; kk++) {
            float4 av = *(float4*)&As[kk][ty*4];
            float4 gv = *(float4*)&Bg[kk][tx*4];
            float4 uv = *(float4*)&Bu[kk][tx*4];
            float aa[4] = {av.x, av.y, av.z, av.w};
            float gg[4] = {gv.x, gv.y, gv.z, gv.w};
            float uu[4] = {uv.x, uv.y, uv.z, uv.w};
            #pragma unroll
            for (int i = 0; i < 4; i++)
                #pragma unroll
                for (int j = 0; j < 4; j++) {
                    ag[i][j] += aa[i] * gg[j];
                    au[i][j] += aa[i] * uu[j];
                }
        }
        __syncthreads();
    }
    #pragma unroll
    for (int i = 0; i < 4; i++) {
        int m = m0 + ty*4 + i;
        float4 o;
        o.x = siluf(ag[i][0]) * au[i][0];
        o.y = siluf(ag[i][1]) * au[i][1];
        o.z = siluf(ag[i][2]) * au[i][2];
        o.w = siluf(ag[i][3]) * au[i][3];
        *(float4*)&g_S1[(size_t)m*SIH + n0 + tx*4] = o;
    }
}

// ---- 5: shared expert GEMM2: shared2[t,h] = S1[t,:]·Wd[h,:],  K=SI, N=H ----
__global__ __launch_bounds__(256) void shared2_kernel(const float* __restrict__ Wd) {
    __shared__ float As[16][68], Bs[16][68];
    int tid = threadIdx.x;
    int tx = tid & 15, ty = tid >> 4;
    int m0 = blockIdx.y * 64, n0 = blockIdx.x * 64;
    int lr = tid >> 2;
    int lc = (tid & 3) * 4;
    float acc[4][4] = {};
    for (int k0 = 0; k0 < SIH; k0 += 16) {
        float4 a = *(const float4*)&g_S1[(size_t)(m0+lr)*SIH + k0 + lc];
        float4 b = *(const float4*)&Wd  [(size_t)(n0+lr)*SIH + k0 + lc];
        As[lc+0][lr]=a.x; As[lc+1][lr]=a.y; As[lc+2][lr]=a.z; As[lc+3][lr]=a.w;
        Bs[lc+0][lr]=b.x; Bs[lc+1][lr]=b.y; Bs[lc+2][lr]=b.z; Bs[lc+3][lr]=b.w;
        __syncthreads();
        #pragma unroll
        for (int kk = 0; kk < 16; kk++) {
            float4 av = *(float4*)&As[kk][ty*4];
            float4 bv = *(float4*)&Bs[kk][tx*4];
            float aa[4] = {av.x, av.y, av.z, av.w};
            float bb[4] = {bv.x, bv.y, bv.z, bv.w};
            #pragma unroll
            for (int i = 0; i < 4; i++)
                #pragma unroll
                for (int j = 0; j < 4; j++)
                    acc[i][j] += aa[i] * bb[j];
        }
        __syncthreads();
    }
    #pragma unroll
    for (int i = 0; i < 4; i++) {
        int m = m0 + ty*4 + i;
        float4 o = {acc[i][0], acc[i][1], acc[i][2], acc[i][3]};
        *(float4*)&g_shared2[(size_t)m*H + n0 + tx*4] = o;
    }
}

// ---- 6: expert GEMM1 (gathered tokens, dual gate/up, SwiGLU * routing weight) ----
// act[p, n] = silu(x[tok,:]·Wgup[e][n,:]) * (x[tok,:]·Wgup[e][I+n,:]) * w_p
__global__ __launch_bounds__(256) void expert1_kernel(const float* __restrict__ x,
                                                      const float* __restrict__ gup) {
    int e = blockIdx.z;
    int cnt = g_count[e];
    int base = g_offset[e];
    int m0 = blockIdx.y * 64;
    if (m0 >= cnt) return;
    int n0 = blockIdx.x * 64;       // n0 < I
    const float* W = gup + (size_t)e * 2 * NI * H;

    __shared__ float As[16][68], Bg[16][68], Bu[16][68];
    int tid = threadIdx.x;
    int tx = tid & 15, ty = tid >> 4;
    int lr = tid >> 2;
    int lc = (tid & 3) * 4;
    int rowidx = m0 + lr;
    int token = (rowidx < cnt) ? g_pair_token[base + rowidx] : -1;
    float ag[4][4] = {}, au[4][4] = {};
    for (int k0 = 0; k0 < H; k0 += 16) {
        float4 a = make_float4(0.f, 0.f, 0.f, 0.f);
        if (token >= 0) a = *(const float4*)&x[(size_t)token*H + k0 + lc];
        float4 bg = *(const float4*)&W[(size_t)(n0+lr)*H      + k0 + lc];
        float4 bu = *(const float4*)&W[(size_t)(NI+n0+lr)*H   + k0 + lc];
        As[lc+0][lr]=a.x;  As[lc+1][lr]=a.y;  As[lc+2][lr]=a.z;  As[lc+3][lr]=a.w;
        Bg[lc+0][lr]=bg.x; Bg[lc+1][lr]=bg.y; Bg[lc+2][lr]=bg.z; Bg[lc+3][lr]=bg.w;
        Bu[lc+0][lr]=bu.x; Bu[lc+1][lr]=bu.y; Bu[lc+2][lr]=bu.z; Bu[lc+3][lr]=bu.w;
        __syncthreads();
        #pragma unroll
        for (int kk = 0; kk < 16; kk++) {
            float4 av = *(float4*)&As[kk][ty*4];
            float4 gv = *(float4*)&Bg[kk][tx*4];
            float4 uv = *(float4*)&Bu[kk][tx*4];
            float aa[4] = {av.x, av.y, av.z, av.w};
            float gg[4] = {gv.x, gv.y, gv.z, gv.w};
            float uu[4] = {uv.x, uv.y, uv.z, uv.w};
            #pragma unroll
            for (int i = 0; i < 4; i++)
                #pragma unroll
                for (int j = 0; j < 4; j++) {
                    ag[i][j] += aa[i] * gg[j];
                    au[i][j] += aa[i] * uu[j];
                }
        }
        __syncthreads();
    }
    #pragma unroll
    for (int i = 0; i < 4; i++) {
        int ridx = m0 + ty*4 + i;
        if (ridx < cnt) {
            int p = base + ridx;
            float w = g_pair_w[p];
            float4 o;
            o.x = siluf(ag[i][0]) * au[i][0] * w;
            o.y = siluf(ag[i][1]) * au[i][1] * w;
            o.z = siluf(ag[i][2]) * au[i][2] * w;
            o.w = siluf(ag[i][3]) * au[i][3] * w;
            *(float4*)&g_act[(size_t)p*NI + n0 + tx*4] = o;
        }
    }
}

// ---- 7: expert GEMM2: pairout[p,h] = act[p,:]·Wdown[e][h,:],  K=I, N=H ----
__global__ __launch_bounds__(256) void expert2_kernel(const float* __restrict__ down) {
    int e = blockIdx.z;
    int cnt = g_count[e];
    int base = g_offset[e];
    int m0 = blockIdx.y * 64;
    if (m0 >= cnt) return;
    int n0 = blockIdx.x * 64;       // n0 < H
    const float* W = down + (size_t)e * H * NI;

    __shared__ float As[16][68], Bs[16][68];
    int tid = threadIdx.x;
    int tx = tid & 15, ty = tid >> 4;
    int lr = tid >> 2;
    int lc = (tid & 3) * 4;
    int rowidx = m0 + lr;
    bool rowok = (rowidx < cnt);
    float acc[4][4] = {};
    for (int k0 = 0; k0 < NI; k0 += 16) {
        float4 a = make_float4(0.f, 0.f, 0.f, 0.f);
        if (rowok) a = *(const float4*)&g_act[(size_t)(base+rowidx)*NI + k0 + lc];
        float4 b = *(const float4*)&W[(size_t)(n0+lr)*NI + k0 + lc];
        As[lc+0][lr]=a.x; As[lc+1][lr]=a.y; As[lc+2][lr]=a.z; As[lc+3][lr]=a.w;
        Bs[lc+0][lr]=b.x; Bs[lc+1][lr]=b.y; Bs[lc+2][lr]=b.z; Bs[lc+3][lr]=b.w;
        __syncthreads();
        #pragma unroll
        for (int kk = 0; kk < 16; kk++) {
            float4 av = *(float4*)&As[kk][ty*4];
            float4 bv = *(float4*)&Bs[kk][tx*4];
            float aa[4] = {av.x, av.y, av.z, av.w};
            float bb[4] = {bv.x, bv.y, bv.z, bv.w};
            #pragma unroll
            for (int i = 0; i < 4; i++)
                #pragma unroll
                for (int j = 0; j < 4; j++)
                    acc[i][j] += aa[i] * bb[j];
        }
        __syncthreads();
    }
    #pragma unroll
    for (int i = 0; i < 4; i++) {
        int ridx = m0 + ty*4 + i;
        if (ridx < cnt) {
            int p = base + ridx;
            float4 o = {acc[i][0], acc[i][1], acc[i][2], acc[i][3]};
            *(float4*)&g_pairout[(size_t)p*H + n0 + tx*4] = o;
        }
    }
}

// ---- 8: combine ----
__global__ void combine_kernel(float* __restrict__ out) {
    int idx = blockIdx.x * blockDim.x + threadIdx.x;   // over T*H/4
    if (idx >= T*H/4) return;
    int t  = idx / (H/4);
    int c4 = (idx % (H/4)) * 4;
    int p0 = g_pos[t*2+0], p1 = g_pos[t*2+1];
    float sgate = 1.f / (1.f + expf(-g_gl[t]));
    float4 a  = *(float4*)&g_pairout[(size_t)p0*H + c4];
    float4 b  = *(float4*)&g_pairout[(size_t)p1*H + c4];
    float4 sh = *(float4*)&g_shared2[(size_t)t*H + c4];
    float4 o;
    o.x = a.x + b.x + sgate * sh.x;
    o.y = a.y + b.y + sgate * sh.y;
    o.z = a.z + b.z + sgate * sh.z;
    o.w = a.w + b.w + sgate * sh.w;
    *(float4*)&out[(size_t)t*H + c4] = o;
}

extern "C" void kernel_launch(void* const* d_in, const int* in_sizes, int n_in,
                              void* d_out, int out_size) {
    const float* x    = (const float*)d_in[0];   // [B,S,H] = [T,H]
    const float* rw   = (const float*)d_in[1];   // [E,H]
    const float* gup  = (const float*)d_in[2];   // [E,2I,H]
    const float* down = (const float*)d_in[3];   // [E,H,I]
    const float* sgw  = (const float*)d_in[4];   // [SI,H]
    const float* suw  = (const float*)d_in[5];   // [SI,H]
    const float* sdw  = (const float*)d_in[6];   // [H,SI]
    const float* seg  = (const float*)d_in[7];   // [1,H]
    float* out = (float*)d_out;

    reset_kernel<<<1, 32>>>();
    router_kernel<<<T/8, 256>>>(x, rw, seg);
    scan_kernel<<<1, 32>>>();
    scatter_kernel<<<T/256, 256>>>();
    shared1_kernel<<<dim3(SIH/64, T/64), 256>>>(x, sgw, suw);
    shared2_kernel<<<dim3(H/64, T/64), 256>>>(sdw);
    expert1_kernel<<<dim3(NI/64, T/64, E), 256>>>(x, gup);
    expert2_kernel<<<dim3(H/64, T/64, E), 256>>>(down);
    combine_kernel<<<(T*H/4 + 255)/256, 256>>>(out);
}

// round 3
// speedup vs baseline: 3.8972x; 3.8972x over previous
#include <cuda_runtime.h>
#include <cuda_fp16.h>
#include <cstdint>
#include <math.h>

#define T 2048
#define H 1024
#define E 8
#define NI 512          // I
#define SIH 2048        // SI
#define NPAIR (2*T)
#define PADROWS (NPAIR+128)

// ---- fp16 operand buffers ----
__device__ __half g_xh [(size_t)T*H];
__device__ __half g_sgw[(size_t)SIH*H];
__device__ __half g_suw[(size_t)SIH*H];
__device__ __half g_sdw[(size_t)H*SIH];
__device__ __half g_gupw[(size_t)E*2*NI*H];
__device__ __half g_dnw[(size_t)E*H*NI];
__device__ __half g_xg [(size_t)PADROWS*H];    // gathered tokens (zero-padded tail)
__device__ __half g_s1h[(size_t)T*SIH];        // shared SwiGLU intermediate (fp16)
__device__ __half g_acth[(size_t)PADROWS*NI];  // expert SwiGLU intermediate (fp16, w-scaled)
// ---- fp32 GEMM outputs ----
__device__ float g_s1g[(size_t)T*SIH];
__device__ float g_s1u[(size_t)T*SIH];
__device__ float g_gu [(size_t)NPAIR*2*NI];
__device__ float g_shared2[(size_t)T*H];
__device__ float g_pairout[(size_t)NPAIR*H];
// ---- routing state ----
__device__ int   g_top_e[T*2];
__device__ float g_top_w[T*2];
__device__ float g_gl[T];
__device__ int   g_count[E];
__device__ int   g_offset[E];
__device__ int   g_fill[E];
__device__ int   g_pair_token[NPAIR];
__device__ float g_pair_w[NPAIR];
__device__ int   g_pos[T*2];

// =============== small kernels ===============
__global__ void reset_kernel() {
    if (threadIdx.x < E) g_count[threadIdx.x] = 0;
}

__global__ void router_kernel(const float* __restrict__ x,
                              const float* __restrict__ rw,
                              const float* __restrict__ seg) {
    int warp = (blockIdx.x * blockDim.x + threadIdx.x) >> 5;
    int lane = threadIdx.x & 31;
    if (warp >= T) return;
    const float* xr = x + (size_t)warp * H;
    float acc[E];
    #pragma unroll
    for (int e = 0; e < E; e++) acc[e] = 0.f;
    float accg = 0.f;
    for (int k = lane; k < H; k += 32) {
        float xv = xr[k];
        #pragma unroll
        for (int e = 0; e < E; e++) acc[e] += xv * rw[e*H + k];
        accg += xv * seg[k];
    }
    #pragma unroll
    for (int o = 16; o > 0; o >>= 1) {
        #pragma unroll
        for (int e = 0; e < E; e++) acc[e] += __shfl_xor_sync(0xffffffffu, acc[e], o);
        accg += __shfl_xor_sync(0xffffffffu, accg, o);
    }
    if (lane == 0) {
        int be = 0; float bv = acc[0];
        #pragma unroll
        for (int e = 1; e < E; e++) if (acc[e] > bv) { bv = acc[e]; be = e; }
        int se = -1; float sv = -1e30f;
        #pragma unroll
        for (int e = 0; e < E; e++) if (e != be && acc[e] > sv) { sv = acc[e]; se = e; }
        float w0 = 1.f / (1.f + expf(sv - bv));
        float w1 = 1.f - w0;
        g_top_e[warp*2+0] = be; g_top_e[warp*2+1] = se;
        g_top_w[warp*2+0] = w0; g_top_w[warp*2+1] = w1;
        g_gl[warp] = accg;
        atomicAdd(&g_count[be], 1);
        atomicAdd(&g_count[se], 1);
    }
}

__global__ void scan_kernel() {
    if (threadIdx.x == 0) {
        int off = 0;
        for (int e = 0; e < E; e++) { g_offset[e] = off; g_fill[e] = off; off += g_count[e]; }
    }
}

__global__ void scatter_kernel() {
    int t = blockIdx.x * blockDim.x + threadIdx.x;
    if (t >= T) return;
    #pragma unroll
    for (int k = 0; k < 2; k++) {
        int e = g_top_e[t*2+k];
        int slot = atomicAdd(&g_fill[e], 1);
        g_pair_token[slot] = t;
        g_pair_w[slot] = g_top_w[t*2+k];
        g_pos[t*2+k] = slot;
    }
}

// fp32 -> fp16 conversion, 8 elements/thread
__device__ __forceinline__ void cvt8(const float* __restrict__ src, __half* __restrict__ dst, size_t i) {
    float4 a = *(const float4*)(src + i);
    float4 b = *(const float4*)(src + i + 4);
    __half h[8];
    h[0]=__float2half_rn(a.x); h[1]=__float2half_rn(a.y); h[2]=__float2half_rn(a.z); h[3]=__float2half_rn(a.w);
    h[4]=__float2half_rn(b.x); h[5]=__float2half_rn(b.y); h[6]=__float2half_rn(b.z); h[7]=__float2half_rn(b.w);
    *(uint4*)(dst + i) = *(uint4*)h;
}
__global__ void cvt_x_k  (const float* s){ size_t i=((size_t)blockIdx.x*blockDim.x+threadIdx.x)*8; if(i<(size_t)T*H)      cvt8(s,g_xh,i); }
__global__ void cvt_sgw_k(const float* s){ size_t i=((size_t)blockIdx.x*blockDim.x+threadIdx.x)*8; if(i<(size_t)SIH*H)    cvt8(s,g_sgw,i); }
__global__ void cvt_suw_k(const float* s){ size_t i=((size_t)blockIdx.x*blockDim.x+threadIdx.x)*8; if(i<(size_t)SIH*H)    cvt8(s,g_suw,i); }
__global__ void cvt_sdw_k(const float* s){ size_t i=((size_t)blockIdx.x*blockDim.x+threadIdx.x)*8; if(i<(size_t)H*SIH)    cvt8(s,g_sdw,i); }
__global__ void cvt_gup_k(const float* s){ size_t i=((size_t)blockIdx.x*blockDim.x+threadIdx.x)*8; if(i<(size_t)E*2*NI*H) cvt8(s,g_gupw,i); }
__global__ void cvt_dn_k (const float* s){ size_t i=((size_t)blockIdx.x*blockDim.x+threadIdx.x)*8; if(i<(size_t)E*H*NI)   cvt8(s,g_dnw,i); }

// gather tokens into compact fp16 rows (+ zero pad rows NPAIR..PADROWS)
__global__ void gather_kernel() {
    size_t i = ((size_t)blockIdx.x*blockDim.x + threadIdx.x) * 8;   // over PADROWS*H
    if (i >= (size_t)PADROWS*H) return;
    int p = (int)(i / H);
    int c = (int)(i % H);
    uint4 v;
    if (p < NPAIR) {
        int t = g_pair_token[p];
        v = *(const uint4*)&g_xh[(size_t)t*H + c];
    } else {
        v = make_uint4(0,0,0,0);
    }
    *(uint4*)&g_xg[i] = v;
}

__device__ __forceinline__ float siluf(float g) { return g / (1.f + expf(-g)); }

// SwiGLU for shared expert: S1h = half(silu(s1g)*s1u)
__global__ void swiglu_shared_kernel() {
    size_t i = ((size_t)blockIdx.x*blockDim.x + threadIdx.x) * 4;
    if (i >= (size_t)T*SIH) return;
    float4 g = *(const float4*)&g_s1g[i];
    float4 u = *(const float4*)&g_s1u[i];
    __half2* dst = (__half2*)&g_s1h[i];
    dst[0] = __floats2half2_rn(siluf(g.x)*u.x, siluf(g.y)*u.y);
    dst[1] = __floats2half2_rn(siluf(g.z)*u.z, siluf(g.w)*u.w);
}

// SwiGLU for experts: act[p, c] = half(silu(gu[p,c]) * gu[p,c+NI] * w_p); pad rows zero
__global__ void swiglu_expert_kernel() {
    size_t i = ((size_t)blockIdx.x*blockDim.x + threadIdx.x) * 4;   // over PADROWS*NI
    if (i >= (size_t)PADROWS*NI) return;
    int p = (int)(i / NI);
    int c = (int)(i % NI);
    __half2* dst = (__half2*)&g_acth[i];
    if (p < NPAIR) {
        const float* row = &g_gu[(size_t)p * (2*NI)];
        float4 g = *(const float4*)&row[c];
        float4 u = *(const float4*)&row[c + NI];
        float w = g_pair_w[p];
        dst[0] = __floats2half2_rn(siluf(g.x)*u.x*w, siluf(g.y)*u.y*w);
        dst[1] = __floats2half2_rn(siluf(g.z)*u.z*w, siluf(g.w)*u.w*w);
    } else {
        dst[0] = __floats2half2_rn(0.f, 0.f);
        dst[1] = __floats2half2_rn(0.f, 0.f);
    }
}

// =============== fp16 MMA GEMM core ===============
// C[M,N](f32) = A[M,K](f16 row-major) @ B[N,K](f16 row-major, i.e. B^T)
// Tile 128x128x32, 8 warps, warp tile 32(M)x64(N), mma.m16n8k16
__device__ __forceinline__ void mma16816(float* c, const uint32_t* a, uint32_t b0, uint32_t b1) {
    asm volatile("mma.sync.aligned.m16n8k16.row.col.f32.f16.f16.f32 "
        "{%0,%1,%2,%3}, {%4,%5,%6,%7}, {%8,%9}, {%0,%1,%2,%3};\n"
        : "+f"(c[0]), "+f"(c[1]), "+f"(c[2]), "+f"(c[3])
        : "r"(a[0]), "r"(a[1]), "r"(a[2]), "r"(a[3]), "r"(b0), "r"(b1));
}

__device__ __forceinline__ void gemm_tile_body(
    const __half* __restrict__ A, const __half* __restrict__ B, float* __restrict__ C,
    int N, int K, int m0, int n0, int rowlim)
{
    __shared__ __half sA[128*40];
    __shared__ __half sB[128*40];
    int tid = threadIdx.x;
    int warp = tid >> 5, lane = tid & 31;
    int wm = warp & 3, wn = warp >> 2;     // 4 warps along M, 2 along N
    int g = lane >> 2, t4 = lane & 3;

    float c[2][8][4];
    #pragma unroll
    for (int im = 0; im < 2; im++)
        #pragma unroll
        for (int in = 0; in < 8; in++)
            #pragma unroll
            for (int q = 0; q < 4; q++) c[im][in][q] = 0.f;

    int r0 = tid >> 2;        // 0..63
    int q0 = tid & 3;         // uint4 within row (32 halfs = 4 x uint4)
    const __half* Ag0 = A + (size_t)(m0 + r0) * K + q0*8;
    const __half* Ag1 = Ag0 + (size_t)64 * K;
    const __half* Bg0 = B + (size_t)(n0 + r0) * K + q0*8;
    const __half* Bg1 = Bg0 + (size_t)64 * K;
    int sOff0 = r0*40 + q0*8;
    int sOff1 = (r0+64)*40 + q0*8;

    uint4 ra0 = *(const uint4*)Ag0;
    uint4 ra1 = *(const uint4*)Ag1;
    uint4 rb0 = *(const uint4*)Bg0;
    uint4 rb1 = *(const uint4*)Bg1;

    for (int kt = 0; kt < K; kt += 32) {
        __syncthreads();
        *(uint4*)(sA + sOff0) = ra0;
        *(uint4*)(sA + sOff1) = ra1;
        *(uint4*)(sB + sOff0) = rb0;
        *(uint4*)(sB + sOff1) = rb1;
        __syncthreads();
        if (kt + 32 < K) {
            ra0 = *(const uint4*)(Ag0 + kt + 32);
            ra1 = *(const uint4*)(Ag1 + kt + 32);
            rb0 = *(const uint4*)(Bg0 + kt + 32);
            rb1 = *(const uint4*)(Bg1 + kt + 32);
        }
        #pragma unroll
        for (int kk = 0; kk < 32; kk += 16) {
            uint32_t af[2][4];
            #pragma unroll
            for (int im = 0; im < 2; im++) {
                const __half* p = sA + (wm*32 + im*16 + g)*40 + kk + t4*2;
                af[im][0] = *(const uint32_t*)p;
                af[im][1] = *(const uint32_t*)(p + 8*40);
                af[im][2] = *(const uint32_t*)(p + 8);
                af[im][3] = *(const uint32_t*)(p + 8*40 + 8);
            }
            #pragma unroll
            for (int in = 0; in < 8; in++) {
                const __half* p = sB + (wn*64 + in*8 + g)*40 + kk + t4*2;
                uint32_t b0 = *(const uint32_t*)p;
                uint32_t b1 = *(const uint32_t*)(p + 8);
                mma16816(c[0][in], af[0], b0, b1);
                mma16816(c[1][in], af[1], b0, b1);
            }
        }
    }

    #pragma unroll
    for (int im = 0; im < 2; im++) {
        int rowa = m0 + wm*32 + im*16 + g;
        int rowb = rowa + 8;
        #pragma unroll
        for (int in = 0; in < 8; in++) {
            int col = n0 + wn*64 + in*8 + t4*2;
            if (rowa < rowlim) *(float2*)&C[(size_t)rowa*N + col] = make_float2(c[im][in][0], c[im][in][1]);
            if (rowb < rowlim) *(float2*)&C[(size_t)rowb*N + col] = make_float2(c[im][in][2], c[im][in][3]);
        }
    }
}

// wrappers binding __device__ global buffers
__global__ __launch_bounds__(256) void gemm_s1g_k() {
    gemm_tile_body(g_xh, g_sgw, g_s1g, SIH, H, blockIdx.y*128, blockIdx.x*128, T);
}
__global__ __launch_bounds__(256) void gemm_s1u_k() {
    gemm_tile_body(g_xh, g_suw, g_s1u, SIH, H, blockIdx.y*128, blockIdx.x*128, T);
}
__global__ __launch_bounds__(256) void gemm_s2_k() {
    gemm_tile_body(g_s1h, g_sdw, g_shared2, H, SIH, blockIdx.y*128, blockIdx.x*128, T);
}
__global__ __launch_bounds__(256) void gemm_e1_k() {
    int e = blockIdx.z;
    int cnt = g_count[e], base = g_offset[e];
    int m0 = blockIdx.y * 128;
    if (m0 >= cnt) return;
    gemm_tile_body(g_xg + (size_t)base*H,
                   g_gupw + (size_t)e*2*NI*H,
                   g_gu + (size_t)base*2*NI,
                   2*NI, H, m0, blockIdx.x*128, cnt);
}
__global__ __launch_bounds__(256) void gemm_e2_k() {
    int e = blockIdx.z;
    int cnt = g_count[e], base = g_offset[e];
    int m0 = blockIdx.y * 128;
    if (m0 >= cnt) return;
    gemm_tile_body(g_acth + (size_t)base*NI,
                   g_dnw + (size_t)e*H*NI,
                   g_pairout + (size_t)base*H,
                   H, NI, m0, blockIdx.x*128, cnt);
}

// =============== combine ===============
__global__ void combine_kernel(float* __restrict__ out) {
    int idx = blockIdx.x * blockDim.x + threadIdx.x;   // over T*H/4
    if (idx >= T*H/4) return;
    int t  = idx / (H/4);
    int c4 = (idx % (H/4)) * 4;
    int p0 = g_pos[t*2+0], p1 = g_pos[t*2+1];
    float sgate = 1.f / (1.f + expf(-g_gl[t]));
    float4 a  = *(float4*)&g_pairout[(size_t)p0*H + c4];
    float4 b  = *(float4*)&g_pairout[(size_t)p1*H + c4];
    float4 sh = *(float4*)&g_shared2[(size_t)t*H + c4];
    float4 o;
    o.x = a.x + b.x + sgate * sh.x;
    o.y = a.y + b.y + sgate * sh.y;
    o.z = a.z + b.z + sgate * sh.z;
    o.w = a.w + b.w + sgate * sh.w;
    *(float4*)&out[(size_t)t*H + c4] = o;
}

extern "C" void kernel_launch(void* const* d_in, const int* in_sizes, int n_in,
                              void* d_out, int out_size) {
    const float* x    = (const float*)d_in[0];   // [T,H]
    const float* rw   = (const float*)d_in[1];   // [E,H]
    const float* gup  = (const float*)d_in[2];   // [E,2I,H]
    const float* down = (const float*)d_in[3];   // [E,H,I]
    const float* sgw  = (const float*)d_in[4];   // [SI,H]
    const float* suw  = (const float*)d_in[5];   // [SI,H]
    const float* sdw  = (const float*)d_in[6];   // [H,SI]
    const float* seg  = (const float*)d_in[7];   // [1,H]
    float* out = (float*)d_out;

    reset_kernel<<<1, 32>>>();
    cvt_x_k  <<<((size_t)T*H/8 + 255)/256, 256>>>(x);
    cvt_sgw_k<<<((size_t)SIH*H/8 + 255)/256, 256>>>(sgw);
    cvt_suw_k<<<((size_t)SIH*H/8 + 255)/256, 256>>>(suw);
    cvt_sdw_k<<<((size_t)H*SIH/8 + 255)/256, 256>>>(sdw);
    cvt_gup_k<<<((size_t)E*2*NI*H/8 + 255)/256, 256>>>(gup);
    cvt_dn_k <<<((size_t)E*H*NI/8 + 255)/256, 256>>>(down);

    router_kernel<<<T/8, 256>>>(x, rw, seg);
    scan_kernel<<<1, 32>>>();
    scatter_kernel<<<T/256, 256>>>();
    gather_kernel<<<((size_t)PADROWS*H/8 + 255)/256, 256>>>();

    gemm_s1g_k<<<dim3(SIH/128, T/128), 256>>>();
    gemm_s1u_k<<<dim3(SIH/128, T/128), 256>>>();
    swiglu_shared_kernel<<<((size_t)T*SIH/4 + 255)/256, 256>>>();
    gemm_s2_k<<<dim3(H/128, T/128), 256>>>();

    gemm_e1_k<<<dim3(2*NI/128, NPAIR/128, E), 256>>>();
    swiglu_expert_kernel<<<((size_t)PADROWS*NI/4 + 255)/256, 256>>>();
    gemm_e2_k<<<dim3(H/128, NPAIR/128, E), 256>>>();

    combine_kernel<<<(T*H/4 + 255)/256, 256>>>(out);
}

// round 4
// speedup vs baseline: 4.0785x; 1.0465x over previous
#include <cuda_runtime.h>
#include <cuda_fp16.h>
#include <cstdint>
#include <math.h>

#define T 2048
#define H 1024
#define E 8
#define NI 512          // I
#define SIH 2048        // SI
#define NPAIR (2*T)

// ---- fp16 operand buffers ----
__device__ __half g_xh [(size_t)T*H];
__device__ __half g_sgw[(size_t)SIH*H];
__device__ __half g_suw[(size_t)SIH*H];
__device__ __half g_sdw[(size_t)H*SIH];
__device__ __half g_gupw[(size_t)E*2*NI*H];
__device__ __half g_dnw[(size_t)E*H*NI];
__device__ __half g_s1h[(size_t)T*SIH];            // shared SwiGLU intermediate (fp16)
__device__ __half g_acth[(size_t)(NPAIR+128)*NI];  // expert SwiGLU intermediate (fp16, w-scaled; +pad rows)
// ---- fp32 GEMM outputs ----
__device__ float g_shared2[(size_t)T*H];
__device__ float g_pairout[(size_t)NPAIR*H];
// ---- routing state ----
__device__ int   g_top_e[T*2];
__device__ float g_top_w[T*2];
__device__ float g_gl[T];
__device__ int   g_count[E];
__device__ int   g_offset[E];
__device__ int   g_fill[E];
__device__ int   g_pair_token[NPAIR];
__device__ float g_pair_w[NPAIR];
__device__ int   g_pos[T*2];

// =============== small kernels ===============
__global__ void reset_kernel() {
    if (threadIdx.x < E) g_count[threadIdx.x] = 0;
}

__global__ void router_kernel(const float* __restrict__ x,
                              const float* __restrict__ rw,
                              const float* __restrict__ seg) {
    int warp = (blockIdx.x * blockDim.x + threadIdx.x) >> 5;
    int lane = threadIdx.x & 31;
    if (warp >= T) return;
    const float* xr = x + (size_t)warp * H;
    float acc[E];
    #pragma unroll
    for (int e = 0; e < E; e++) acc[e] = 0.f;
    float accg = 0.f;
    for (int k = lane; k < H; k += 32) {
        float xv = xr[k];
        #pragma unroll
        for (int e = 0; e < E; e++) acc[e] += xv * rw[e*H + k];
        accg += xv * seg[k];
    }
    #pragma unroll
    for (int o = 16; o > 0; o >>= 1) {
        #pragma unroll
        for (int e = 0; e < E; e++) acc[e] += __shfl_xor_sync(0xffffffffu, acc[e], o);
        accg += __shfl_xor_sync(0xffffffffu, accg, o);
    }
    if (lane == 0) {
        int be = 0; float bv = acc[0];
        #pragma unroll
        for (int e = 1; e < E; e++) if (acc[e] > bv) { bv = acc[e]; be = e; }
        int se = -1; float sv = -1e30f;
        #pragma unroll
        for (int e = 0; e < E; e++) if (e != be && acc[e] > sv) { sv = acc[e]; se = e; }
        float w0 = 1.f / (1.f + expf(sv - bv));
        float w1 = 1.f - w0;
        g_top_e[warp*2+0] = be; g_top_e[warp*2+1] = se;
        g_top_w[warp*2+0] = w0; g_top_w[warp*2+1] = w1;
        g_gl[warp] = accg;
        atomicAdd(&g_count[be], 1);
        atomicAdd(&g_count[se], 1);
    }
}

__global__ void scan_kernel() {
    if (threadIdx.x == 0) {
        int off = 0;
        for (int e = 0; e < E; e++) { g_offset[e] = off; g_fill[e] = off; off += g_count[e]; }
    }
}

__global__ void scatter_kernel() {
    int t = blockIdx.x * blockDim.x + threadIdx.x;
    if (t >= T) return;
    #pragma unroll
    for (int k = 0; k < 2; k++) {
        int e = g_top_e[t*2+k];
        int slot = atomicAdd(&g_fill[e], 1);
        g_pair_token[slot] = t;
        g_pair_w[slot] = g_top_w[t*2+k];
        g_pos[t*2+k] = slot;
    }
}

// fp32 -> fp16 conversion, 8 elements/thread
__device__ __forceinline__ void cvt8(const float* __restrict__ src, __half* __restrict__ dst, size_t i) {
    float4 a = *(const float4*)(src + i);
    float4 b = *(const float4*)(src + i + 4);
    __half h[8];
    h[0]=__float2half_rn(a.x); h[1]=__float2half_rn(a.y); h[2]=__float2half_rn(a.z); h[3]=__float2half_rn(a.w);
    h[4]=__float2half_rn(b.x); h[5]=__float2half_rn(b.y); h[6]=__float2half_rn(b.z); h[7]=__float2half_rn(b.w);
    *(uint4*)(dst + i) = *(uint4*)h;
}
__global__ void cvt_x_k  (const float* s){ size_t i=((size_t)blockIdx.x*blockDim.x+threadIdx.x)*8; if(i<(size_t)T*H)      cvt8(s,g_xh,i); }
__global__ void cvt_sgw_k(const float* s){ size_t i=((size_t)blockIdx.x*blockDim.x+threadIdx.x)*8; if(i<(size_t)SIH*H)    cvt8(s,g_sgw,i); }
__global__ void cvt_suw_k(const float* s){ size_t i=((size_t)blockIdx.x*blockDim.x+threadIdx.x)*8; if(i<(size_t)SIH*H)    cvt8(s,g_suw,i); }
__global__ void cvt_sdw_k(const float* s){ size_t i=((size_t)blockIdx.x*blockDim.x+threadIdx.x)*8; if(i<(size_t)H*SIH)    cvt8(s,g_sdw,i); }
__global__ void cvt_gup_k(const float* s){ size_t i=((size_t)blockIdx.x*blockDim.x+threadIdx.x)*8; if(i<(size_t)E*2*NI*H) cvt8(s,g_gupw,i); }
__global__ void cvt_dn_k (const float* s){ size_t i=((size_t)blockIdx.x*blockDim.x+threadIdx.x)*8; if(i<(size_t)E*H*NI)   cvt8(s,g_dnw,i); }

__device__ __forceinline__ float siluf(float g) { return g / (1.f + expf(-g)); }

__device__ __forceinline__ void mma16816(float* c, const uint32_t* a, uint32_t b0, uint32_t b1) {
    asm volatile("mma.sync.aligned.m16n8k16.row.col.f32.f16.f16.f32 "
        "{%0,%1,%2,%3}, {%4,%5,%6,%7}, {%8,%9}, {%0,%1,%2,%3};\n"
        : "+f"(c[0]), "+f"(c[1]), "+f"(c[2]), "+f"(c[3])
        : "r"(a[0]), "r"(a[1]), "r"(a[2]), "r"(a[3]), "r"(b0), "r"(b1));
}

// =============== dual-B GEMM + SwiGLU epilogue ===============
// Computes G = A@Bg^T, U = A@Bu^T over a 128(M)x64(N) tile, K-loop in 32-chunks,
// then writes half( silu(G)*U*w[row] ) to Cout. Optional token indirection on A rows.
__device__ __forceinline__ void gemm_dual_body(
    const __half* __restrict__ A, const int* __restrict__ tokmap,
    const __half* __restrict__ Bg, const __half* __restrict__ Bu,
    __half* __restrict__ Cout, int ldo, const float* __restrict__ wrow,
    int K, int m0, int n0, int rowlim)
{
    __shared__ __half sA [128*40];
    __shared__ __half sBg[64*40];
    __shared__ __half sBu[64*40];
    int tid = threadIdx.x;
    int warp = tid >> 5, lane = tid & 31;
    int wm = warp & 3, wn = warp >> 2;     // 4 warps along M, 2 along N
    int g = lane >> 2, t4 = lane & 3;

    float cg[2][4][4] = {}, cu[2][4][4] = {};

    int r0 = tid >> 2;        // 0..63
    int q0 = tid & 3;
    int rowA0 = m0 + r0, rowA1 = m0 + r0 + 64;
    bool ok0 = rowA0 < rowlim, ok1 = rowA1 < rowlim;
    const __half* Ag0 = A + (size_t)(ok0 ? (tokmap ? tokmap[rowA0] : rowA0) : 0) * K + q0*8;
    const __half* Ag1 = A + (size_t)(ok1 ? (tokmap ? tokmap[rowA1] : rowA1) : 0) * K + q0*8;
    const __half* Bgp = Bg + (size_t)(n0 + r0) * K + q0*8;
    const __half* Bup = Bu + (size_t)(n0 + r0) * K + q0*8;
    int sOffA0 = r0*40 + q0*8;
    int sOffA1 = (r0+64)*40 + q0*8;
    int sOffB  = r0*40 + q0*8;

    uint4 zz = make_uint4(0,0,0,0);
    uint4 ra0 = ok0 ? *(const uint4*)Ag0 : zz;
    uint4 ra1 = ok1 ? *(const uint4*)Ag1 : zz;
    uint4 rg  = *(const uint4*)Bgp;
    uint4 ru  = *(const uint4*)Bup;

    for (int kt = 0; kt < K; kt += 32) {
        __syncthreads();
        *(uint4*)(sA  + sOffA0) = ra0;
        *(uint4*)(sA  + sOffA1) = ra1;
        *(uint4*)(sBg + sOffB)  = rg;
        *(uint4*)(sBu + sOffB)  = ru;
        __syncthreads();
        if (kt + 32 < K) {
            ra0 = ok0 ? *(const uint4*)(Ag0 + kt + 32) : zz;
            ra1 = ok1 ? *(const uint4*)(Ag1 + kt + 32) : zz;
            rg  = *(const uint4*)(Bgp + kt + 32);
            ru  = *(const uint4*)(Bup + kt + 32);
        }
        #pragma unroll
        for (int kk = 0; kk < 32; kk += 16) {
            uint32_t af[2][4];
            #pragma unroll
            for (int im = 0; im < 2; im++) {
                const __half* p = sA + (wm*32 + im*16 + g)*40 + kk + t4*2;
                af[im][0] = *(const uint32_t*)p;
                af[im][1] = *(const uint32_t*)(p + 8*40);
                af[im][2] = *(const uint32_t*)(p + 8);
                af[im][3] = *(const uint32_t*)(p + 8*40 + 8);
            }
            #pragma unroll
            for (int in = 0; in < 4; in++) {
                const __half* pg = sBg + (wn*32 + in*8 + g)*40 + kk + t4*2;
                const __half* pu = sBu + (wn*32 + in*8 + g)*40 + kk + t4*2;
                uint32_t bg0 = *(const uint32_t*)pg;
                uint32_t bg1 = *(const uint32_t*)(pg + 8);
                uint32_t bu0 = *(const uint32_t*)pu;
                uint32_t bu1 = *(const uint32_t*)(pu + 8);
                mma16816(cg[0][in], af[0], bg0, bg1);
                mma16816(cg[1][in], af[1], bg0, bg1);
                mma16816(cu[0][in], af[0], bu0, bu1);
                mma16816(cu[1][in], af[1], bu0, bu1);
            }
        }
    }

    #pragma unroll
    for (int im = 0; im < 2; im++) {
        int rowa = m0 + wm*32 + im*16 + g;
        int rowb = rowa + 8;
        float wa = 1.f, wb = 1.f;
        if (wrow) {
            if (rowa < rowlim) wa = wrow[rowa];
            if (rowb < rowlim) wb = wrow[rowb];
        }
        #pragma unroll
        for (int in = 0; in < 4; in++) {
            int col = n0 + wn*32 + in*8 + t4*2;
            if (rowa < rowlim) {
                float v0 = siluf(cg[im][in][0]) * cu[im][in][0] * wa;
                float v1 = siluf(cg[im][in][1]) * cu[im][in][1] * wa;
                *(__half2*)&Cout[(size_t)rowa*ldo + col] = __floats2half2_rn(v0, v1);
            }
            if (rowb < rowlim) {
                float v0 = siluf(cg[im][in][2]) * cu[im][in][2] * wb;
                float v1 = siluf(cg[im][in][3]) * cu[im][in][3] * wb;
                *(__half2*)&Cout[(size_t)rowb*ldo + col] = __floats2half2_rn(v0, v1);
            }
        }
    }
}

// =============== single GEMM (fp32 out) ===============
// C[M,N](f32) = A[M,K](f16) @ B[N,K](f16)^T ; tile 128x128x32, warp tile 32x64
__device__ __forceinline__ void gemm_tile_body(
    const __half* __restrict__ A, const __half* __restrict__ B, float* __restrict__ C,
    int N, int K, int m0, int n0, int rowlim)
{
    __shared__ __half sA[128*40];
    __shared__ __half sB[128*40];
    int tid = threadIdx.x;
    int warp = tid >> 5, lane = tid & 31;
    int wm = warp & 3, wn = warp >> 2;
    int g = lane >> 2, t4 = lane & 3;

    float c[2][8][4] = {};

    int r0 = tid >> 2;
    int q0 = tid & 3;
    const __half* Ag0 = A + (size_t)(m0 + r0) * K + q0*8;
    const __half* Ag1 = Ag0 + (size_t)64 * K;
    const __half* Bg0 = B + (size_t)(n0 + r0) * K + q0*8;
    const __half* Bg1 = Bg0 + (size_t)64 * K;
    int sOff0 = r0*40 + q0*8;
    int sOff1 = (r0+64)*40 + q0*8;

    uint4 ra0 = *(const uint4*)Ag0;
    uint4 ra1 = *(const uint4*)Ag1;
    uint4 rb0 = *(const uint4*)Bg0;
    uint4 rb1 = *(const uint4*)Bg1;

    for (int kt = 0; kt < K; kt += 32) {
        __syncthreads();
        *(uint4*)(sA + sOff0) = ra0;
        *(uint4*)(sA + sOff1) = ra1;
        *(uint4*)(sB + sOff0) = rb0;
        *(uint4*)(sB + sOff1) = rb1;
        __syncthreads();
        if (kt + 32 < K) {
            ra0 = *(const uint4*)(Ag0 + kt + 32);
            ra1 = *(const uint4*)(Ag1 + kt + 32);
            rb0 = *(const uint4*)(Bg0 + kt + 32);
            rb1 = *(const uint4*)(Bg1 + kt + 32);
        }
        #pragma unroll
        for (int kk = 0; kk < 32; kk += 16) {
            uint32_t af[2][4];
            #pragma unroll
            for (int im = 0; im < 2; im++) {
                const __half* p = sA + (wm*32 + im*16 + g)*40 + kk + t4*2;
                af[im][0] = *(const uint32_t*)p;
                af[im][1] = *(const uint32_t*)(p + 8*40);
                af[im][2] = *(const uint32_t*)(p + 8);
                af[im][3] = *(const uint32_t*)(p + 8*40 + 8);
            }
            #pragma unroll
            for (int in = 0; in < 8; in++) {
                const __half* p = sB + (wn*64 + in*8 + g)*40 + kk + t4*2;
                uint32_t b0 = *(const uint32_t*)p;
                uint32_t b1 = *(const uint32_t*)(p + 8);
                mma16816(c[0][in], af[0], b0, b1);
                mma16816(c[1][in], af[1], b0, b1);
            }
        }
    }

    #pragma unroll
    for (int im = 0; im < 2; im++) {
        int rowa = m0 + wm*32 + im*16 + g;
        int rowb = rowa + 8;
        #pragma unroll
        for (int in = 0; in < 8; in++) {
            int col = n0 + wn*64 + in*8 + t4*2;
            if (rowa < rowlim) *(float2*)&C[(size_t)rowa*N + col] = make_float2(c[im][in][0], c[im][in][1]);
            if (rowb < rowlim) *(float2*)&C[(size_t)rowb*N + col] = make_float2(c[im][in][2], c[im][in][3]);
        }
    }
}

// =============== GEMM wrappers ===============
// shared expert gate+up fused: g_s1h[t,n] = half(silu(x·Wg)*(x·Wu))
__global__ __launch_bounds__(256) void gemm_s1_k() {
    gemm_dual_body(g_xh, nullptr, g_sgw, g_suw, g_s1h, SIH, nullptr,
                   H, blockIdx.y*128, blockIdx.x*64, T);
}
// shared expert down: g_shared2 = g_s1h @ g_sdw^T
__global__ __launch_bounds__(256) void gemm_s2_k() {
    gemm_tile_body(g_s1h, g_sdw, g_shared2, H, SIH, blockIdx.y*128, blockIdx.x*128, T);
}
// expert gate+up fused with token gather + routing-weight epilogue
__global__ __launch_bounds__(256) void gemm_e1_k() {
    int e = blockIdx.z;
    int cnt = g_count[e], base = g_offset[e];
    int m0 = blockIdx.y * 128;
    if (m0 >= cnt) return;
    const __half* W = g_gupw + (size_t)e * 2 * NI * H;
    gemm_dual_body(g_xh, g_pair_token + base, W, W + (size_t)NI * H,
                   g_acth + (size_t)base * NI, NI, g_pair_w + base,
                   H, m0, blockIdx.x*64, cnt);
}
// expert down: g_pairout = g_acth @ g_dnw^T  (pad rows in g_acth may be stale; rows>=cnt never written)
__global__ __launch_bounds__(256) void gemm_e2_k() {
    int e = blockIdx.z;
    int cnt = g_count[e], base = g_offset[e];
    int m0 = blockIdx.y * 128;
    if (m0 >= cnt) return;
    gemm_tile_body(g_acth + (size_t)base*NI,
                   g_dnw + (size_t)e*H*NI,
                   g_pairout + (size_t)base*H,
                   H, NI, m0, blockIdx.x*128, cnt);
}

// =============== combine ===============
__global__ void combine_kernel(float* __restrict__ out) {
    int idx = blockIdx.x * blockDim.x + threadIdx.x;   // over T*H/4
    if (idx >= T*H/4) return;
    int t  = idx / (H/4);
    int c4 = (idx % (H/4)) * 4;
    int p0 = g_pos[t*2+0], p1 = g_pos[t*2+1];
    float sgate = 1.f / (1.f + expf(-g_gl[t]));
    float4 a  = *(float4*)&g_pairout[(size_t)p0*H + c4];
    float4 b  = *(float4*)&g_pairout[(size_t)p1*H + c4];
    float4 sh = *(float4*)&g_shared2[(size_t)t*H + c4];
    float4 o;
    o.x = a.x + b.x + sgate * sh.x;
    o.y = a.y + b.y + sgate * sh.y;
    o.z = a.z + b.z + sgate * sh.z;
    o.w = a.w + b.w + sgate * sh.w;
    *(float4*)&out[(size_t)t*H + c4] = o;
}

extern "C" void kernel_launch(void* const* d_in, const int* in_sizes, int n_in,
                              void* d_out, int out_size) {
    const float* x    = (const float*)d_in[0];   // [T,H]
    const float* rw   = (const float*)d_in[1];   // [E,H]
    const float* gup  = (const float*)d_in[2];   // [E,2I,H]
    const float* down = (const float*)d_in[3];   // [E,H,I]
    const float* sgw  = (const float*)d_in[4];   // [SI,H]
    const float* suw  = (const float*)d_in[5];   // [SI,H]
    const float* sdw  = (const float*)d_in[6];   // [H,SI]
    const float* seg  = (const float*)d_in[7];   // [1,H]
    float* out = (float*)d_out;

    reset_kernel<<<1, 32>>>();
    cvt_x_k  <<<((size_t)T*H/8 + 255)/256, 256>>>(x);
    cvt_sgw_k<<<((size_t)SIH*H/8 + 255)/256, 256>>>(sgw);
    cvt_suw_k<<<((size_t)SIH*H/8 + 255)/256, 256>>>(suw);
    cvt_sdw_k<<<((size_t)H*SIH/8 + 255)/256, 256>>>(sdw);
    cvt_gup_k<<<((size_t)E*2*NI*H/8 + 255)/256, 256>>>(gup);
    cvt_dn_k <<<((size_t)E*H*NI/8 + 255)/256, 256>>>(down);

    router_kernel<<<T/8, 256>>>(x, rw, seg);
    scan_kernel<<<1, 32>>>();
    scatter_kernel<<<T/256, 256>>>();

    gemm_s1_k<<<dim3(SIH/64, T/128), 256>>>();
    gemm_s2_k<<<dim3(H/128, T/128), 256>>>();

    gemm_e1_k<<<dim3(NI/64, NPAIR/128, E), 256>>>();
    gemm_e2_k<<<dim3(H/128, NPAIR/128, E), 256>>>();

    combine_kernel<<<(T*H/4 + 255)/256, 256>>>(out);
}

// round 6
// speedup vs baseline: 5.0515x; 1.2386x over previous
#include <cuda_runtime.h>
#include <cuda_fp16.h>
#include <cstdint>
#include <math.h>

#define T 2048
#define H 1024
#define E 8
#define NI 512          // I
#define SIH 2048        // SI
#define NPAIR (2*T)

// ---- fp16 operand buffers ----
__device__ __half g_xh [(size_t)T*H];
__device__ __half g_sgw[(size_t)SIH*H];
__device__ __half g_suw[(size_t)SIH*H];
__device__ __half g_sdw[(size_t)H*SIH];
__device__ __half g_gupw[(size_t)E*2*NI*H];
__device__ __half g_dnw[(size_t)E*H*NI];
__device__ __half g_s1h[(size_t)T*SIH];            // shared SwiGLU intermediate (fp16)
__device__ __half g_acth[(size_t)(NPAIR+128)*NI];  // expert SwiGLU intermediate (fp16, w-scaled; +pad rows)
// ---- fp32 GEMM outputs ----
__device__ float g_shared2[(size_t)T*H];
__device__ float g_pairout[(size_t)NPAIR*H];
// ---- routing state ----
__device__ int   g_top_e[T*2];
__device__ float g_top_w[T*2];
__device__ float g_gl[T];
__device__ int   g_count[E];
__device__ int   g_offset[E];
__device__ int   g_fill[E];
__device__ int   g_pair_token[NPAIR];
__device__ float g_pair_w[NPAIR];
__device__ int   g_pos[T*2];

// =============== PTX helpers ===============
__device__ __forceinline__ uint32_t smem_u32(const void* p) {
    uint32_t a;
    asm("{ .reg .u64 t; cvta.to.shared.u64 t, %1; cvt.u32.u64 %0, t; }" : "=r"(a) : "l"(p));
    return a;
}
__device__ __forceinline__ void cp16(uint32_t dst, const void* src) {
    asm volatile("cp.async.cg.shared.global [%0], [%1], 16;" :: "r"(dst), "l"(src) : "memory");
}
#define CP_COMMIT() asm volatile("cp.async.commit_group;" ::: "memory")
#define CP_WAIT0()  asm volatile("cp.async.wait_group 0;" ::: "memory")

__device__ __forceinline__ void ldsm_x4(uint32_t& r0, uint32_t& r1, uint32_t& r2, uint32_t& r3, uint32_t addr) {
    asm volatile("ldmatrix.sync.aligned.m8n8.x4.shared.b16 {%0,%1,%2,%3}, [%4];"
        : "=r"(r0), "=r"(r1), "=r"(r2), "=r"(r3) : "r"(addr));
}
__device__ __forceinline__ void mma16816(float* c, const uint32_t* a, uint32_t b0, uint32_t b1) {
    asm volatile("mma.sync.aligned.m16n8k16.row.col.f32.f16.f16.f32 "
        "{%0,%1,%2,%3}, {%4,%5,%6,%7}, {%8,%9}, {%0,%1,%2,%3};\n"
        : "+f"(c[0]), "+f"(c[1]), "+f"(c[2]), "+f"(c[3])
        : "r"(a[0]), "r"(a[1]), "r"(a[2]), "r"(a[3]), "r"(b0), "r"(b1));
}

__device__ __forceinline__ float siluf(float g) { return g / (1.f + expf(-g)); }

// =============== GEMM core: 128(M) x 128(B-rows) x K, k-chunk 32, 2-stage cp.async, ldmatrix ===============
// DUAL=0: C[M,128] fp32, B tile = 128 rows of Bg starting at nb.
// DUAL=1: C[M,64] fp16 = silu(G)*U*w; B tile rows r: h=r>>6, s=r&63:
//         s<32 -> gate row nb+h*32+s ; s>=32 -> up row nb+h*32+s-32.
template<int DUAL>
__device__ __forceinline__ void gemm_body(
    const __half* __restrict__ A, const int* __restrict__ tokmap,
    const __half* __restrict__ Bg, const __half* __restrict__ Bu,
    void* __restrict__ Cout, int ldo, const float* __restrict__ wrow,
    int K, int m0, int nb, int rowlim)
{
    __shared__ __half sA[2][128*40];
    __shared__ __half sB[2][128*40];
    int tid = threadIdx.x;
    int warp = tid >> 5, lane = tid & 31;
    int wm = warp & 3, wn = warp >> 2;          // 4 warps M, 2 warps N(B-rows/2)
    int g = lane >> 2, t4 = lane & 3;

    float c[2][8][4] = {};

    // ---- cp.async loaders: 512 16B-chunks per operand per stage, 256 threads x 2 ----
    const __half* asrc[2]; uint32_t adst[2];
    const __half* bsrc[2]; uint32_t bdst[2];
    uint32_t sAb[2] = { smem_u32(sA[0]), smem_u32(sA[1]) };
    uint32_t sBb[2] = { smem_u32(sB[0]), smem_u32(sB[1]) };
    #pragma unroll
    for (int i = 0; i < 2; i++) {
        int idx = i*256 + tid;
        int r = idx >> 2, cq = idx & 3;          // row, 16B chunk within 64B
        int gr = m0 + r;
        int srow;
        if (tokmap) srow = (gr < rowlim) ? tokmap[gr] : 0;
        else        srow = gr;                   // buffers padded so OOB rows are readable
        asrc[i] = A + (size_t)srow * K + cq*8;
        adst[i] = (uint32_t)(r*40 + cq*8) * 2;
        const __half* brow;
        if (DUAL) {
            int h = r >> 6, s = r & 63;
            brow = (s < 32) ? (Bg + (size_t)(nb + h*32 + s) * K)
                            : (Bu + (size_t)(nb + h*32 + s - 32) * K);
        } else {
            brow = Bg + (size_t)(nb + r) * K;
        }
        bsrc[i] = brow + cq*8;
        bdst[i] = (uint32_t)(r*40 + cq*8) * 2;
    }

    // ---- ldmatrix per-lane byte offsets ----
    int lrow = lane & 15, lc8 = (lane >> 4) * 8;
    uint32_t aoff[2], boff[4];
    #pragma unroll
    for (int im = 0; im < 2; im++) aoff[im] = (uint32_t)((wm*32 + im*16 + lrow)*40 + lc8) * 2;
    #pragma unroll
    for (int j = 0; j < 4; j++)    boff[j]  = (uint32_t)((wn*64 + j*16  + lrow)*40 + lc8) * 2;

    int NK = K / 32;
    // prologue: stage 0
    #pragma unroll
    for (int i = 0; i < 2; i++) { cp16(sAb[0]+adst[i], asrc[i]); cp16(sBb[0]+bdst[i], bsrc[i]); }
    CP_COMMIT();

    for (int kt = 0; kt < NK; kt++) {
        CP_WAIT0();
        __syncthreads();
        int cur = kt & 1;
        if (kt + 1 < NK) {
            int nxt = cur ^ 1, ko = (kt+1)*32;
            #pragma unroll
            for (int i = 0; i < 2; i++) { cp16(sAb[nxt]+adst[i], asrc[i]+ko); cp16(sBb[nxt]+bdst[i], bsrc[i]+ko); }
        }
        CP_COMMIT();
        #pragma unroll
        for (int kk = 0; kk < 32; kk += 16) {
            uint32_t a0[4], a1[4];
            ldsm_x4(a0[0], a0[1], a0[2], a0[3], sAb[cur] + aoff[0] + kk*2);
            ldsm_x4(a1[0], a1[1], a1[2], a1[3], sAb[cur] + aoff[1] + kk*2);
            #pragma unroll
            for (int j = 0; j < 4; j++) {
                uint32_t r0, r1, r2, r3;
                ldsm_x4(r0, r1, r2, r3, sBb[cur] + boff[j] + kk*2);
                mma16816(c[0][2*j],   a0, r0, r2);
                mma16816(c[0][2*j+1], a0, r1, r3);
                mma16816(c[1][2*j],   a1, r0, r2);
                mma16816(c[1][2*j+1], a1, r1, r3);
            }
        }
    }

    // ---- epilogue ----
    #pragma unroll
    for (int im = 0; im < 2; im++) {
        int rowa = m0 + wm*32 + im*16 + g;
        int rowb = rowa + 8;
        if (DUAL) {
            float wa = 1.f, wb = 1.f;
            if (wrow) {
                if (rowa < rowlim) wa = wrow[rowa];
                if (rowb < rowlim) wb = wrow[rowb];
            }
            __half* Co = (__half*)Cout;
            #pragma unroll
            for (int in = 0; in < 4; in++) {
                int col = nb + wn*32 + in*8 + t4*2;
                if (rowa < rowlim) {
                    float v0 = siluf(c[im][in][0]) * c[im][in+4][0] * wa;
                    float v1 = siluf(c[im][in][1]) * c[im][in+4][1] * wa;
                    *(__half2*)&Co[(size_t)rowa*ldo + col] = __floats2half2_rn(v0, v1);
                }
                if (rowb < rowlim) {
                    float v0 = siluf(c[im][in][2]) * c[im][in+4][2] * wb;
                    float v1 = siluf(c[im][in][3]) * c[im][in+4][3] * wb;
                    *(__half2*)&Co[(size_t)rowb*ldo + col] = __floats2half2_rn(v0, v1);
                }
            }
        } else {
            float* Co = (float*)Cout;
            #pragma unroll
            for (int in = 0; in < 8; in++) {
                int col = nb + wn*64 + in*8 + t4*2;
                if (rowa < rowlim) *(float2*)&Co[(size_t)rowa*ldo + col] = make_float2(c[im][in][0], c[im][in][1]);
                if (rowb < rowlim) *(float2*)&Co[(size_t)rowb*ldo + col] = make_float2(c[im][in][2], c[im][in][3]);
            }
        }
    }
}

// =============== GEMM wrappers ===============
__global__ __launch_bounds__(256) void gemm_s1_k() {   // fused shared gate+up -> g_s1h
    gemm_body<1>(g_xh, nullptr, g_sgw, g_suw, g_s1h, SIH, nullptr,
                 H, blockIdx.y*128, blockIdx.x*64, T);
}
__global__ __launch_bounds__(256) void gemm_s2_k() {   // shared down -> g_shared2
    gemm_body<0>(g_s1h, nullptr, g_sdw, nullptr, g_shared2, H, nullptr,
                 SIH, blockIdx.y*128, blockIdx.x*128, T);
}
__global__ __launch_bounds__(256) void gemm_e1_k() {   // expert gate+up (gathered) -> g_acth
    int e = blockIdx.z;
    int cnt = g_count[e], base = g_offset[e];
    int m0 = blockIdx.y * 128;
    if (m0 >= cnt) return;
    const __half* W = g_gupw + (size_t)e * 2 * NI * H;
    gemm_body<1>(g_xh, g_pair_token + base, W, W + (size_t)NI * H,
                 g_acth + (size_t)base * NI, NI, g_pair_w + base,
                 H, m0, blockIdx.x*64, cnt);
}
__global__ __launch_bounds__(256) void gemm_e2_k() {   // expert down -> g_pairout
    int e = blockIdx.z;
    int cnt = g_count[e], base = g_offset[e];
    int m0 = blockIdx.y * 128;
    if (m0 >= cnt) return;
    gemm_body<0>(g_acth + (size_t)base * NI, nullptr, g_dnw + (size_t)e * H * NI, nullptr,
                 g_pairout + (size_t)base * H, H, nullptr,
                 NI, m0, blockIdx.x*128, cnt);
}

// =============== small kernels ===============
__global__ void reset_kernel() {
    if (threadIdx.x < E) g_count[threadIdx.x] = 0;
}

__global__ void router_kernel(const float* __restrict__ x,
                              const float* __restrict__ rw,
                              const float* __restrict__ seg) {
    int warp = (blockIdx.x * blockDim.x + threadIdx.x) >> 5;
    int lane = threadIdx.x & 31;
    if (warp >= T) return;
    const float* xr = x + (size_t)warp * H;
    float acc[E];
    #pragma unroll
    for (int e = 0; e < E; e++) acc[e] = 0.f;
    float accg = 0.f;
    for (int k = lane; k < H; k += 32) {
        float xv = xr[k];
        #pragma unroll
        for (int e = 0; e < E; e++) acc[e] += xv * rw[e*H + k];
        accg += xv * seg[k];
    }
    #pragma unroll
    for (int o = 16; o > 0; o >>= 1) {
        #pragma unroll
        for (int e = 0; e < E; e++) acc[e] += __shfl_xor_sync(0xffffffffu, acc[e], o);
        accg += __shfl_xor_sync(0xffffffffu, accg, o);
    }
    if (lane == 0) {
        int be = 0; float bv = acc[0];
        #pragma unroll
        for (int e = 1; e < E; e++) if (acc[e] > bv) { bv = acc[e]; be = e; }
        int se = -1; float sv = -1e30f;
        #pragma unroll
        for (int e = 0; e < E; e++) if (e != be && acc[e] > sv) { sv = acc[e]; se = e; }
        float w0 = 1.f / (1.f + expf(sv - bv));
        float w1 = 1.f - w0;
        g_top_e[warp*2+0] = be; g_top_e[warp*2+1] = se;
        g_top_w[warp*2+0] = w0; g_top_w[warp*2+1] = w1;
        g_gl[warp] = accg;
        atomicAdd(&g_count[be], 1);
        atomicAdd(&g_count[se], 1);
    }
}

__global__ void scan_kernel() {
    if (threadIdx.x == 0) {
        int off = 0;
        for (int e = 0; e < E; e++) { g_offset[e] = off; g_fill[e] = off; off += g_count[e]; }
    }
}

__global__ void scatter_kernel() {
    int t = blockIdx.x * blockDim.x + threadIdx.x;
    if (t >= T) return;
    #pragma unroll
    for (int k = 0; k < 2; k++) {
        int e = g_top_e[t*2+k];
        int slot = atomicAdd(&g_fill[e], 1);
        g_pair_token[slot] = t;
        g_pair_w[slot] = g_top_w[t*2+k];
        g_pos[t*2+k] = slot;
    }
}

// fp32 -> fp16 conversion, 8 elements/thread; single fused kernel over all operands
__device__ __forceinline__ void cvt8(const float* __restrict__ src, __half* __restrict__ dst, size_t i) {
    float4 a = *(const float4*)(src + i);
    float4 b = *(const float4*)(src + i + 4);
    __half h[8];
    h[0]=__float2half_rn(a.x); h[1]=__float2half_rn(a.y); h[2]=__float2half_rn(a.z); h[3]=__float2half_rn(a.w);
    h[4]=__float2half_rn(b.x); h[5]=__float2half_rn(b.y); h[6]=__float2half_rn(b.z); h[7]=__float2half_rn(b.w);
    *(uint4*)(dst + i) = *(uint4*)h;
}
#define SZ_X   ((size_t)T*H)
#define SZ_SGW ((size_t)SIH*H)
#define SZ_SUW ((size_t)SIH*H)
#define SZ_SDW ((size_t)H*SIH)
#define SZ_GUP ((size_t)E*2*NI*H)
#define SZ_DN  ((size_t)E*H*NI)
#define C0 (SZ_X)
#define C1 (C0+SZ_SGW)
#define C2 (C1+SZ_SUW)
#define C3 (C2+SZ_SDW)
#define C4 (C3+SZ_GUP)
#define C5 (C4+SZ_DN)
__global__ void cvt_all_k(const float* __restrict__ x,   const float* __restrict__ sgw,
                          const float* __restrict__ suw, const float* __restrict__ sdw,
                          const float* __restrict__ gup, const float* __restrict__ dn) {
    size_t i = ((size_t)blockIdx.x * blockDim.x + threadIdx.x) * 8;
    if (i >= C5) return;
    if      (i < C0) cvt8(x,   g_xh,   i);
    else if (i < C1) cvt8(sgw, g_sgw,  i - C0);
    else if (i < C2) cvt8(suw, g_suw,  i - C1);
    else if (i < C3) cvt8(sdw, g_sdw,  i - C2);
    else if (i < C4) cvt8(gup, g_gupw, i - C3);
    else             cvt8(dn,  g_dnw,  i - C4);
}

// =============== combine ===============
__global__ void combine_kernel(float* __restrict__ out) {
    int idx = blockIdx.x * blockDim.x + threadIdx.x;   // over T*H/4
    if (idx >= T*H/4) return;
    int t  = idx / (H/4);
    int c4 = (idx % (H/4)) * 4;
    int p0 = g_pos[t*2+0], p1 = g_pos[t*2+1];
    float sgate = 1.f / (1.f + expf(-g_gl[t]));
    float4 a  = *(float4*)&g_pairout[(size_t)p0*H + c4];
    float4 b  = *(float4*)&g_pairout[(size_t)p1*H + c4];
    float4 sh = *(float4*)&g_shared2[(size_t)t*H + c4];
    float4 o;
    o.x = a.x + b.x + sgate * sh.x;
    o.y = a.y + b.y + sgate * sh.y;
    o.z = a.z + b.z + sgate * sh.z;
    o.w = a.w + b.w + sgate * sh.w;
    *(float4*)&out[(size_t)t*H + c4] = o;
}

extern "C" void kernel_launch(void* const* d_in, const int* in_sizes, int n_in,
                              void* d_out, int out_size) {
    const float* x    = (const float*)d_in[0];   // [T,H]
    const float* rw   = (const float*)d_in[1];   // [E,H]
    const float* gup  = (const float*)d_in[2];   // [E,2I,H]
    const float* down = (const float*)d_in[3];   // [E,H,I]
    const float* sgw  = (const float*)d_in[4];   // [SI,H]
    const float* suw  = (const float*)d_in[5];   // [SI,H]
    const float* sdw  = (const float*)d_in[6];   // [H,SI]
    const float* seg  = (const float*)d_in[7];   // [1,H]
    float* out = (float*)d_out;

    reset_kernel<<<1, 32>>>();
    cvt_all_k<<<(unsigned)((C5/8 + 255)/256), 256>>>(x, sgw, suw, sdw, gup, down);

    router_kernel<<<T/8, 256>>>(x, rw, seg);
    scan_kernel<<<1, 32>>>();
    scatter_kernel<<<T/256, 256>>>();

    gemm_s1_k<<<dim3(SIH/64, T/128), 256>>>();
    gemm_s2_k<<<dim3(H/128, T/128), 256>>>();

    gemm_e1_k<<<dim3(NI/64, NPAIR/128, E), 256>>>();
    gemm_e2_k<<<dim3(H/128, NPAIR/128, E), 256>>>();

    combine_kernel<<<(T*H/4 + 255)/256, 256>>>(out);
}